// round 15
// baseline (speedup 1.0000x reference)
#include <cuda_runtime.h>
#include <math.h>
#include <stdint.h>

#define BB 64
#define SS 1024
#define PP 32
#define EE 128
#define HH 256
#define G4 1024
#define NJB 64
#define NBLK 128
#define SWS2 776

#define SM_ACT 0
#define SM_W   24576
#define SM_Z   (SM_W + 16*SWS2)
#define SM_R   (SM_Z + 8192)
#define SM_M   (SM_R + 8192)
#define SMEM_FLOATS (SM_M + 128)
#define SMEM_BYTES (SMEM_FLOATS * 4)

__device__ float    g_xT[SS * EE * BB];
__device__ float    g_h[2 * 2 * HH * BB];
__device__ float    g_bias[2 * G4];
__device__ float    g_Wt[2 * NJB * 16 * 384 * 2];
__device__ unsigned g_spanmaskT[SS * BB];
__device__ int      g_cnt[BB * PP];
__device__ float    g_reps[BB * PP * 2 * HH];
__device__ unsigned g_arrive[2 * NJB];

__global__ void k_prep(const float* bih_f, const float* bhh_f,
                       const float* bih_b, const float* bhh_b,
                       const float* Wih_f, const float* Whh_f,
                       const float* Wih_b, const float* Whh_b) {
    int i0 = blockIdx.x * blockDim.x + threadIdx.x;
    int stride = gridDim.x * blockDim.x;
    if (i0 < 2 * NJB) g_arrive[i0] = 0;
    for (int i = i0; i < 2 * 2 * HH * BB; i += stride) g_h[i] = 0.f;
    for (int i = i0; i < BB * PP;         i += stride) g_cnt[i] = 0;
    for (int i = i0; i < 2 * G4;          i += stride)
        g_bias[i] = (i < G4) ? (bih_f[i] + bhh_f[i]) : (bih_b[i - G4] + bhh_b[i - G4]);
    for (int idx = i0; idx < 2 * NJB * 16 * 384; idx += stride) {
        int k   = idx % 384;
        int r   = idx / 384;
        int c   = r % 16;
        int jb  = (r / 16) % NJB;
        int dir = r / (16 * NJB);
        int zcol = (c >> 2) * HH + jb * 4 + (c & 3);
        const float* Wih = dir ? Wih_b : Wih_f;
        const float* Whh = dir ? Whh_b : Whh_f;
        float v = (k < EE) ? Wih[zcol * EE + k] : Whh[zcol * HH + (k - EE)];
        g_Wt[idx * 2 + 0] = v;
        g_Wt[idx * 2 + 1] = v;
    }
}

__global__ void k_embed(const float* emb, const int* ids) {
    __shared__ float tile[128 * 65];
    __shared__ int sid[64];
    int s = blockIdx.x, t = threadIdx.x;
    if (t < 64) sid[t] = ids[t * SS + s];
    __syncthreads();
    for (int i = t; i < 8192; i += 256) {
        int b = i >> 7, e = i & 127;
        tile[e * 65 + b] = emb[sid[b] * EE + e];
    }
    __syncthreads();
    float* dst = g_xT + s * (EE * BB);
    for (int i = t; i < 8192; i += 256)
        dst[i] = tile[(i >> 6) * 65 + (i & 63)];
}

__global__ void k_span(const int* offmap, const int* positions) {
    int idx = blockIdx.x * blockDim.x + threadIdx.x;
    if (idx >= BB * SS) return;
    int b = idx / SS;
    int s = idx % SS;
    int os = offmap[idx * 2], oe = offmap[idx * 2 + 1];
    unsigned m = 0;
    for (int p = 0; p < PP; p++) {
        int ps = positions[(b * PP + p) * 2];
        int pe = positions[(b * PP + p) * 2 + 1];
        if (os >= ps && oe <= pe) {
            m |= (1u << p);
            atomicAdd(&g_cnt[b * PP + p], 1);
        }
    }
    g_spanmaskT[s * BB + b] = m;
}

__device__ __forceinline__ void ffma2(unsigned long long& d,
                                      unsigned long long a,
                                      unsigned long long b) {
    asm("fma.rn.f32x2 %0, %1, %2, %0;" : "+l"(d) : "l"(a), "l"(b));
}
__device__ __forceinline__ void cpasync16(uint32_t saddr, const void* gaddr) {
    asm volatile("cp.async.cg.shared.global [%0], [%1], 16;" :: "r"(saddr), "l"(gaddr));
}
__device__ __forceinline__ void cpasync_commit() { asm volatile("cp.async.commit_group;"); }
__device__ __forceinline__ void cpasync_wait2()  { asm volatile("cp.async.wait_group 2;"); }
__device__ __forceinline__ void cpasync_wait1()  { asm volatile("cp.async.wait_group 1;"); }
__device__ __forceinline__ void cpasync_wait0()  { asm volatile("cp.async.wait_group 0;"); }
__device__ __forceinline__ void st_release_gpu(unsigned* p, unsigned v) {
    asm volatile("st.release.gpu.global.u32 [%0], %1;" :: "l"(p), "r"(v) : "memory");
}
__device__ __forceinline__ unsigned ld_acquire_gpu(const unsigned* p) {
    unsigned v;
    asm volatile("ld.acquire.gpu.global.u32 %0, [%1];" : "=r"(v) : "l"(p) : "memory");
    return v;
}
__device__ __forceinline__ void barx(int id, int cnt) {
    asm volatile("bar.sync %0, %1;" :: "r"(id), "r"(cnt) : "memory");
}
__device__ __forceinline__ float sigmoidf_(float x) { return 1.f / (1.f + __expf(-x)); }
__device__ __forceinline__ float tanhf_(float x) {
    float xc = fminf(fmaxf(x, -15.f), 15.f);
    float e = __expf(2.f * xc);
    return (e - 1.f) / (e + 1.f);
}

__device__ __forceinline__ void gemm_range(const float* __restrict__ sAct,
                                           const float* __restrict__ sW2,
                                           int ct, int b0, int kbeg, int kend,
                                           unsigned long long acc[4][2]) {
    const float* abase = sAct + b0;
    #pragma unroll 2
    for (int k = kbeg; k < kend; k += 4) {
        ulonglong2 a0 = *(const ulonglong2*)(abase + (k + 0) * BB);
        ulonglong2 a1 = *(const ulonglong2*)(abase + (k + 1) * BB);
        ulonglong2 a2 = *(const ulonglong2*)(abase + (k + 2) * BB);
        ulonglong2 a3 = *(const ulonglong2*)(abase + (k + 3) * BB);
        #pragma unroll
        for (int r = 0; r < 4; r++) {
            const float* wb = sW2 + (ct * 4 + r) * SWS2 + k * 2;
            ulonglong2 w01 = *(const ulonglong2*)(wb);
            ulonglong2 w23 = *(const ulonglong2*)(wb + 4);
            ffma2(acc[r][0], w01.x, a0.x); ffma2(acc[r][1], w01.x, a0.y);
            ffma2(acc[r][0], w01.y, a1.x); ffma2(acc[r][1], w01.y, a1.y);
            ffma2(acc[r][0], w23.x, a2.x); ffma2(acc[r][1], w23.x, a2.y);
            ffma2(acc[r][0], w23.y, a3.x); ffma2(acc[r][1], w23.y, a3.y);
        }
    }
}

extern __shared__ float smem[];

// Warp roles: pairs 0-3 (warps 0-7, low arbiter prio) = x-engine (32 x-rows each).
// Pairs 4-7 (warps 8-15, high prio) = gates/publish/release, zero x work.
__global__ void __launch_bounds__(512, 1) k_lstm(int nsteps) {
    float*    sAct = smem + SM_ACT;              // [384][64]
    float*    sW2  = smem + SM_W;                // [16][SWS2]
    float*    sZP  = smem + SM_Z;                // [8 kq][16][64]
    float*    sR   = smem + SM_R;                // [32 p][4 u][64 b]
    unsigned* sM   = (unsigned*)(smem + SM_M);   // [2][64]

    const int t   = threadIdx.x;
    const int jb  = blockIdx.x & (NJB - 1);
    const int dir = blockIdx.x >> 6;
    unsigned* slots = g_arrive + dir * NJB;

    {   // weights resident in smem for the whole run
        const float4* wsrc = (const float4*)(g_Wt + (size_t)(dir * NJB + jb) * 16 * 384 * 2);
        float4* wdst = (float4*)sW2;
        for (int i = t; i < 3072; i += 512) {
            int c = i / 192, j = i % 192;
            wdst[c * (SWS2 / 4) + j] = wsrc[i];
        }
    }
    for (int i = t; i < 8192; i += 512) sR[i] = 0.f;

    // roles
    const int kq      = t >> 6;          // pair 0..7
    const int tp      = t & 63;
    const int ct      = tp >> 4;         // gate 0..3
    const int b0      = (tp & 15) * 4;
    const int hb      = 128 + kq * 32;   // h K-range (32 rows, all pairs)
    const bool is_x   = (kq < 4);        // x-engine pairs
    const int xb      = kq * 32;         // x K-range (32 rows, pairs 0-3 only)
    const int pbar    = 8 + kq;          // named barrier per pair

    // gates roles (t>=256): 1 cell per thread
    const int u  = kq - 4;               // valid for gates pairs
    const int gb = tp;
    float bvg[4];
    if (t >= 256) {
        #pragma unroll
        for (int g = 0; g < 4; g++)
            bvg[g] = g_bias[dir * G4 + g * HH + jb * 4 + u];
    }
    float creg = 0.f;

    const uint32_t sact_b = (uint32_t)__cvta_generic_to_shared(sAct);
    const uint32_t sm_b   = (uint32_t)__cvta_generic_to_shared(sM);

    unsigned long long acc[4][2];

    // prologue: x pairs stage x(0) (own 32-row slice, 8 each); gates threads 256-271 stage mask(0)
    {
        int s0 = dir ? (SS - 1) : 0;
        const float* xsrc = g_xT + (size_t)s0 * (EE * BB);
        if (is_x) {
            #pragma unroll
            for (int i = 0; i < 8; i++) {
                int fi = kq * 2048 + (i * 64 + tp) * 4;
                cpasync16(sact_b + (uint32_t)fi * 4, xsrc + fi);
            }
        }
        if (t >= 256 && t < 272)
            cpasync16(sm_b + (uint32_t)(t - 256) * 16, g_spanmaskT + s0 * BB + (t - 256) * 4);
        cpasync_commit();
    }
    cpasync_wait0();
    __syncthreads();
    #pragma unroll
    for (int r = 0; r < 4; r++) { acc[r][0] = 0ull; acc[r][1] = 0ull; }
    if (is_x)
        gemm_range(sAct, sW2, ct, b0, xb, xb + 32, acc);
    barx(pbar, 64);                    // pair done reading its x(0) slice
    if (nsteps > 1 && is_x) {          // prefetch x(1) [group X]
        int s1 = dir ? (SS - 2) : 1;
        const float* xsrc = g_xT + (size_t)s1 * (EE * BB);
        #pragma unroll
        for (int i = 0; i < 8; i++) {
            int fi = kq * 2048 + (i * 64 + tp) * 4;
            cpasync16(sact_b + (uint32_t)fi * 4, xsrc + fi);
        }
    }
    cpasync_commit();

    for (int step = 0; step < nsteps; step++) {
        const int par = step & 1;

        // 1. slot barrier (only 64 threads poll)
        if (t < NJB) {
            while ((int)ld_acquire_gpu(slots + t) < step) { }
        }
        __syncthreads();

        // 2. pair-local h staging in TWO waves (groups A, B)
        {
            const float* hsrc = g_h + (dir * 2 + par) * (HH * BB);
            #pragma unroll
            for (int i = 0; i < 4; i++) {                 // wave A: rows hb..hb+16
                int fi = kq * 2048 + (i * 64 + tp) * 4;
                cpasync16(sact_b + (uint32_t)(8192 + fi) * 4, hsrc + fi);
            }
            cpasync_commit();
            #pragma unroll
            for (int i = 4; i < 8; i++) {                 // wave B: rows hb+16..hb+32
                int fi = kq * 2048 + (i * 64 + tp) * 4;
                cpasync16(sact_b + (uint32_t)(8192 + fi) * 4, hsrc + fi);
            }
            cpasync_commit();
        }

        // 3. x + mask prefetch for step+1 (group X)
        if (step + 1 < nsteps) {
            int s_next = dir ? (SS - 2 - step) : (step + 1);
            if (is_x) {
                const float* xsrc = g_xT + (size_t)s_next * (EE * BB);
                #pragma unroll
                for (int i = 0; i < 8; i++) {
                    int fi = kq * 2048 + (i * 64 + tp) * 4;
                    cpasync16(sact_b + (uint32_t)fi * 4, xsrc + fi);
                }
            }
            if (t >= 256 && t < 272)
                cpasync16(sm_b + (uint32_t)((par ^ 1) * 64 + (t - 256) * 4) * 4,
                          g_spanmaskT + s_next * BB + (t - 256) * 4);
        }
        cpasync_commit();

        // 4. h-GEMM: wave A while wave B lands, then wave B
        cpasync_wait2();                  // A complete (B, X may be pending)
        barx(pbar, 64);
        gemm_range(sAct, sW2, ct, b0, hb, hb + 16, acc);
        cpasync_wait1();                  // B complete (X may be pending)
        barx(pbar, 64);
        gemm_range(sAct, sW2, ct, b0, hb + 16, hb + 32, acc);

        // 5. K-eighth partials; block-wide join
        #pragma unroll
        for (int r = 0; r < 4; r++) {
            float2 lo = *(float2*)&acc[r][0];
            float2 hi = *(float2*)&acc[r][1];
            *(float4*)&sZP[kq * 1024 + (ct * 4 + r) * 64 + b0] =
                make_float4(lo.x, lo.y, hi.x, hi.y);
        }
        #pragma unroll
        for (int r = 0; r < 4; r++) { acc[r][0] = 0ull; acc[r][1] = 0ull; }
        __syncthreads();

        // 6. gates (warps 8-15, high prio) -> h publish -> release
        if (t >= 256) {
            float z[4];
            #pragma unroll
            for (int g = 0; g < 4; g++) {
                float s = bvg[g];
                #pragma unroll
                for (int q = 0; q < 8; q++)
                    s += sZP[q * 1024 + (g * 4 + u) * 64 + gb];
                z[g] = s;
            }
            float ii = sigmoidf_(z[0]);
            float ff = sigmoidf_(z[1]);
            float gg = tanhf_(z[2]);
            float oo = sigmoidf_(z[3]);
            float cn = ff * creg + ii * gg;
            creg = cn;
            float hn = oo * tanhf_(cn);
            int j = jb * 4 + u;
            __stcg(&g_h[((dir * 2 + (par ^ 1)) * HH + j) * BB + gb], hn);
            barx(1, 256);                       // all 256 h stores issued
            if (t == 256) {
                asm volatile("membar.gl;" ::: "memory");
                st_release_gpu(slots + jb, (unsigned)(step + 1));
            }
            // off-critical-path span accumulation
            unsigned m = sM[par * 64 + gb];
            while (m) {
                int p = __ffs(m) - 1;
                m &= m - 1;
                sR[p * 256 + u * 64 + gb] += hn;
            }
        }

        // 7. x-engine pairs: trailing x-GEMM for step+1 (runs during gates);
        //    gates pairs just retire their group and head to the next poll.
        cpasync_wait0();
        barx(pbar, 64);
        if (is_x && step + 1 < nsteps)
            gemm_range(sAct, sW2, ct, b0, xb, xb + 32, acc);
    }

    __syncthreads();
    for (int i = t; i < 8192; i += 512) {
        int p = i >> 8, uu = (i >> 6) & 3, b = i & 63;
        g_reps[(b * PP + p) * (2 * HH) + dir * HH + jb * 4 + uu] = sR[i];
    }
}

__global__ void k_final(const float* fc_w, const float* fc_b,
                        const int* positions, float* out) {
    int bp = blockIdx.x;
    int t = threadIdx.x;
    __shared__ float red[128];
    float s = 0.f;
    for (int d = t; d < 2 * HH; d += 128)
        s += g_reps[bp * (2 * HH) + d] * fc_w[d];
    red[t] = s;
    __syncthreads();
    for (int o = 64; o > 0; o >>= 1) {
        if (t < o) red[t] += red[t + o];
        __syncthreads();
    }
    if (t == 0) {
        int cnt = g_cnt[bp];
        int ps = positions[bp * 2], pe = positions[bp * 2 + 1];
        bool valid = (cnt > 0) && !(ps == 0 && pe == 0);
        float v = valid ? red[0] / fmaxf((float)cnt, 1.f) : 0.f;
        out[bp] = v + fc_b[0];
    }
}

extern "C" void kernel_launch(void* const* d_in, const int* in_sizes, int n_in,
                              void* d_out, int out_size) {
    const float* emb    = (const float*)d_in[0];
    const float* Wih_f  = (const float*)d_in[1];
    const float* Whh_f  = (const float*)d_in[2];
    const float* bih_f  = (const float*)d_in[3];
    const float* bhh_f  = (const float*)d_in[4];
    const float* Wih_b  = (const float*)d_in[5];
    const float* Whh_b  = (const float*)d_in[6];
    const float* bih_b  = (const float*)d_in[7];
    const float* bhh_b  = (const float*)d_in[8];
    const float* fc_w   = (const float*)d_in[9];
    const float* fc_b   = (const float*)d_in[10];
    const int* input_ids = (const int*)d_in[11];
    const int* offmap    = (const int*)d_in[13];
    const int* positions = (const int*)d_in[14];
    float* out = (float*)d_out;

    cudaFuncSetAttribute(k_lstm, cudaFuncAttributeMaxDynamicSharedMemorySize, SMEM_BYTES);

    k_prep<<<1024, 256>>>(bih_f, bhh_f, bih_b, bhh_b, Wih_f, Whh_f, Wih_b, Whh_b);
    k_embed<<<SS, 256>>>(emb, input_ids);
    k_span<<<(BB * SS) / 256, 256>>>(offmap, positions);
    k_lstm<<<NBLK, 512, SMEM_BYTES>>>(SS);
    k_final<<<BB * PP, 128>>>(fc_w, fc_b, positions, out);
}

// round 16
// speedup vs baseline: 1.9145x; 1.9145x over previous
#include <cuda_runtime.h>
#include <math.h>
#include <stdint.h>

#define BB 64
#define SS 1024
#define PP 32
#define EE 128
#define HH 256
#define G4 1024
#define NJB 64
#define NBLK 128
#define SWS2 776

#define SM_ACT 0
#define SM_W   24576
#define SM_Z   (SM_W + 16*SWS2)
#define SM_R   (SM_Z + 8192)
#define SM_M   (SM_R + 8192)
#define SMEM_FLOATS (SM_M + 128)
#define SMEM_BYTES (SMEM_FLOATS * 4)

__device__ float    g_xT[SS * EE * BB];
__device__ float    g_h[2 * 2 * HH * BB];
__device__ float    g_bias[2 * G4];
__device__ float    g_Wt[2 * NJB * 16 * 384 * 2];
__device__ unsigned g_spanmaskT[SS * BB];
__device__ int      g_cnt[BB * PP];
__device__ float    g_reps[BB * PP * 2 * HH];
__device__ unsigned g_arrive[2 * NJB];

__global__ void k_prep(const float* bih_f, const float* bhh_f,
                       const float* bih_b, const float* bhh_b,
                       const float* Wih_f, const float* Whh_f,
                       const float* Wih_b, const float* Whh_b) {
    int i0 = blockIdx.x * blockDim.x + threadIdx.x;
    int stride = gridDim.x * blockDim.x;
    if (i0 < 2 * NJB) g_arrive[i0] = 0;
    for (int i = i0; i < 2 * 2 * HH * BB; i += stride) g_h[i] = 0.f;
    for (int i = i0; i < BB * PP;         i += stride) g_cnt[i] = 0;
    for (int i = i0; i < 2 * G4;          i += stride)
        g_bias[i] = (i < G4) ? (bih_f[i] + bhh_f[i]) : (bih_b[i - G4] + bhh_b[i - G4]);
    for (int idx = i0; idx < 2 * NJB * 16 * 384; idx += stride) {
        int k   = idx % 384;
        int r   = idx / 384;
        int c   = r % 16;
        int jb  = (r / 16) % NJB;
        int dir = r / (16 * NJB);
        int zcol = (c >> 2) * HH + jb * 4 + (c & 3);
        const float* Wih = dir ? Wih_b : Wih_f;
        const float* Whh = dir ? Whh_b : Whh_f;
        float v = (k < EE) ? Wih[zcol * EE + k] : Whh[zcol * HH + (k - EE)];
        g_Wt[idx * 2 + 0] = v;
        g_Wt[idx * 2 + 1] = v;
    }
}

__global__ void k_embed(const float* emb, const int* ids) {
    __shared__ float tile[128 * 65];
    __shared__ int sid[64];
    int s = blockIdx.x, t = threadIdx.x;
    if (t < 64) sid[t] = ids[t * SS + s];
    __syncthreads();
    for (int i = t; i < 8192; i += 256) {
        int b = i >> 7, e = i & 127;
        tile[e * 65 + b] = emb[sid[b] * EE + e];
    }
    __syncthreads();
    float* dst = g_xT + s * (EE * BB);
    for (int i = t; i < 8192; i += 256)
        dst[i] = tile[(i >> 6) * 65 + (i & 63)];
}

__global__ void k_span(const int* offmap, const int* positions) {
    int idx = blockIdx.x * blockDim.x + threadIdx.x;
    if (idx >= BB * SS) return;
    int b = idx / SS;
    int s = idx % SS;
    int os = offmap[idx * 2], oe = offmap[idx * 2 + 1];
    unsigned m = 0;
    for (int p = 0; p < PP; p++) {
        int ps = positions[(b * PP + p) * 2];
        int pe = positions[(b * PP + p) * 2 + 1];
        if (os >= ps && oe <= pe) {
            m |= (1u << p);
            atomicAdd(&g_cnt[b * PP + p], 1);
        }
    }
    g_spanmaskT[s * BB + b] = m;
}

__device__ __forceinline__ void ffma2(unsigned long long& d,
                                      unsigned long long a,
                                      unsigned long long b) {
    asm("fma.rn.f32x2 %0, %1, %2, %0;" : "+l"(d) : "l"(a), "l"(b));
}
__device__ __forceinline__ void cpasync16(uint32_t saddr, const void* gaddr) {
    asm volatile("cp.async.cg.shared.global [%0], [%1], 16;" :: "r"(saddr), "l"(gaddr));
}
__device__ __forceinline__ void cpasync_commit() { asm volatile("cp.async.commit_group;"); }
__device__ __forceinline__ void cpasync_wait2()  { asm volatile("cp.async.wait_group 2;"); }
__device__ __forceinline__ void cpasync_wait1()  { asm volatile("cp.async.wait_group 1;"); }
__device__ __forceinline__ void cpasync_wait0()  { asm volatile("cp.async.wait_group 0;"); }
__device__ __forceinline__ void st_release_gpu(unsigned* p, unsigned v) {
    asm volatile("st.release.gpu.global.u32 [%0], %1;" :: "l"(p), "r"(v) : "memory");
}
__device__ __forceinline__ unsigned ld_acquire_gpu(const unsigned* p) {
    unsigned v;
    asm volatile("ld.acquire.gpu.global.u32 %0, [%1];" : "=r"(v) : "l"(p) : "memory");
    return v;
}
__device__ __forceinline__ void barx(int id, int cnt) {
    asm volatile("bar.sync %0, %1;" :: "r"(id), "r"(cnt) : "memory");
}
// fast activations: __expf (EX2-based) + __fdividef (RCP-based) — no div.rn chains
__device__ __forceinline__ float sigmoidf_(float x) {
    return __fdividef(1.f, 1.f + __expf(-x));
}
__device__ __forceinline__ float tanhf_(float x) {
    float xc = fminf(fmaxf(x, -15.f), 15.f);
    float e = __expf(2.f * xc);
    return __fdividef(e - 1.f, e + 1.f);
}

__device__ __forceinline__ void gemm_range(const float* __restrict__ sAct,
                                           const float* __restrict__ sW2,
                                           int ct, int b0, int kbeg, int kend,
                                           unsigned long long acc[4][2]) {
    const float* abase = sAct + b0;
    #pragma unroll 2
    for (int k = kbeg; k < kend; k += 4) {
        ulonglong2 a0 = *(const ulonglong2*)(abase + (k + 0) * BB);
        ulonglong2 a1 = *(const ulonglong2*)(abase + (k + 1) * BB);
        ulonglong2 a2 = *(const ulonglong2*)(abase + (k + 2) * BB);
        ulonglong2 a3 = *(const ulonglong2*)(abase + (k + 3) * BB);
        #pragma unroll
        for (int r = 0; r < 4; r++) {
            const float* wb = sW2 + (ct * 4 + r) * SWS2 + k * 2;
            ulonglong2 w01 = *(const ulonglong2*)(wb);
            ulonglong2 w23 = *(const ulonglong2*)(wb + 4);
            ffma2(acc[r][0], w01.x, a0.x); ffma2(acc[r][1], w01.x, a0.y);
            ffma2(acc[r][0], w01.y, a1.x); ffma2(acc[r][1], w01.y, a1.y);
            ffma2(acc[r][0], w23.x, a2.x); ffma2(acc[r][1], w23.x, a2.y);
            ffma2(acc[r][0], w23.y, a3.x); ffma2(acc[r][1], w23.y, a3.y);
        }
    }
}

extern __shared__ float smem[];

__global__ void __launch_bounds__(512, 1) k_lstm(int nsteps) {
    float*    sAct = smem + SM_ACT;              // [384][64]
    float*    sW2  = smem + SM_W;                // [16][SWS2]
    float*    sZP  = smem + SM_Z;                // [8 kq][16][64]
    float*    sR   = smem + SM_R;                // [32 p][4 u][64 b]
    unsigned* sM   = (unsigned*)(smem + SM_M);   // [2][64]

    const int t   = threadIdx.x;
    const int jb  = blockIdx.x & (NJB - 1);
    const int dir = blockIdx.x >> 6;
    unsigned* slots = g_arrive + dir * NJB;

    {   // weights resident in smem for the whole run
        const float4* wsrc = (const float4*)(g_Wt + (size_t)(dir * NJB + jb) * 16 * 384 * 2);
        float4* wdst = (float4*)sW2;
        for (int i = t; i < 3072; i += 512) {
            int c = i / 192, j = i % 192;
            wdst[c * (SWS2 / 4) + j] = wsrc[i];
        }
    }
    for (int i = t; i < 8192; i += 512) sR[i] = 0.f;

    // roles (R11 balanced schedule)
    const int kq    = t >> 6;          // warp-pair id 0..7
    const int tp    = t & 63;
    const int ct    = tp >> 4;         // gate 0..3
    const int b0    = (tp & 15) * 4;
    const int hb    = 128 + kq * 32;   // h K-range (32 rows per pair)
    const int xb    = kq * 16;         // x K-range (16 rows per pair)
    const int pbar  = 8 + kq;          // named barrier per pair

    // gates roles (t<256): 1 cell per thread
    const int u  = (t >> 6) & 3;
    const int gb = t & 63;
    float bvg[4];
    if (t < 256) {
        #pragma unroll
        for (int g = 0; g < 4; g++)
            bvg[g] = g_bias[dir * G4 + g * HH + jb * 4 + u];
    }
    float creg = 0.f;

    const uint32_t sact_b = (uint32_t)__cvta_generic_to_shared(sAct);
    const uint32_t sm_b   = (uint32_t)__cvta_generic_to_shared(sM);

    unsigned long long acc[4][2];

    // prologue: pair-local x(step0) + mask(step0) into buffer 0, x-GEMM(0)
    {
        int s0 = dir ? (SS - 1) : 0;
        const float* xsrc = g_xT + (size_t)s0 * (EE * BB);
        #pragma unroll
        for (int i = 0; i < 4; i++) {
            int fi = kq * 1024 + (i * 64 + tp) * 4;
            cpasync16(sact_b + (uint32_t)fi * 4, xsrc + fi);
        }
        if (t < 16)
            cpasync16(sm_b + (uint32_t)t * 16, g_spanmaskT + s0 * BB + t * 4);
        cpasync_commit();
    }
    cpasync_wait0();
    __syncthreads();
    #pragma unroll
    for (int r = 0; r < 4; r++) { acc[r][0] = 0ull; acc[r][1] = 0ull; }
    gemm_range(sAct, sW2, ct, b0, xb, xb + 16, acc);
    barx(pbar, 64);                    // pair done reading x(0) slice
    if (nsteps > 1) {                  // prefetch x(1) [group X]
        int s1 = dir ? (SS - 2) : 1;
        const float* xsrc = g_xT + (size_t)s1 * (EE * BB);
        #pragma unroll
        for (int i = 0; i < 4; i++) {
            int fi = kq * 1024 + (i * 64 + tp) * 4;
            cpasync16(sact_b + (uint32_t)fi * 4, xsrc + fi);
        }
    }
    cpasync_commit();

    for (int step = 0; step < nsteps; step++) {
        const int par = step & 1;

        // 1. slot barrier (only 64 threads poll)
        if (t < NJB) {
            while ((int)ld_acquire_gpu(slots + t) < step) { }
        }
        __syncthreads();

        // 2. pair-local h staging in TWO waves (groups A, B)
        {
            const float* hsrc = g_h + (dir * 2 + par) * (HH * BB);
            #pragma unroll
            for (int i = 0; i < 4; i++) {                 // wave A: rows hb..hb+16
                int fi = kq * 2048 + (i * 64 + tp) * 4;
                cpasync16(sact_b + (uint32_t)(8192 + fi) * 4, hsrc + fi);
            }
            cpasync_commit();
            #pragma unroll
            for (int i = 4; i < 8; i++) {                 // wave B: rows hb+16..hb+32
                int fi = kq * 2048 + (i * 64 + tp) * 4;
                cpasync16(sact_b + (uint32_t)(8192 + fi) * 4, hsrc + fi);
            }
            cpasync_commit();
        }

        // 3. x + mask prefetch for step+1 hoisted here (group X)
        if (step + 1 < nsteps) {
            int s_next = dir ? (SS - 2 - step) : (step + 1);
            const float* xsrc = g_xT + (size_t)s_next * (EE * BB);
            #pragma unroll
            for (int i = 0; i < 4; i++) {
                int fi = kq * 1024 + (i * 64 + tp) * 4;
                cpasync16(sact_b + (uint32_t)fi * 4, xsrc + fi);
            }
            if (t < 16)
                cpasync16(sm_b + (uint32_t)((par ^ 1) * 64 + t * 4) * 4,
                          g_spanmaskT + s_next * BB + t * 4);
        }
        cpasync_commit();

        // 4. h-GEMM: wave A while wave B lands, then wave B
        cpasync_wait2();                  // A complete (B, X may be pending)
        barx(pbar, 64);
        gemm_range(sAct, sW2, ct, b0, hb, hb + 16, acc);
        cpasync_wait1();                  // B complete (X may be pending)
        barx(pbar, 64);
        gemm_range(sAct, sW2, ct, b0, hb + 16, hb + 32, acc);

        // 5. K-eighth partials; block-wide join
        #pragma unroll
        for (int r = 0; r < 4; r++) {
            float2 lo = *(float2*)&acc[r][0];
            float2 hi = *(float2*)&acc[r][1];
            *(float4*)&sZP[kq * 1024 + (ct * 4 + r) * 64 + b0] =
                make_float4(lo.x, lo.y, hi.x, hi.y);
        }
        #pragma unroll
        for (int r = 0; r < 4; r++) { acc[r][0] = 0ull; acc[r][1] = 0ull; }
        __syncthreads();

        // 6. gates (warps 0-7); warps 8-15 fall through to trailing x-GEMM
        if (t < 256) {
            unsigned m = sM[par * 64 + gb];   // hoisted: overlap with z reduction
            float z[4];
            #pragma unroll
            for (int g = 0; g < 4; g++) {
                float s = bvg[g];
                #pragma unroll
                for (int q = 0; q < 8; q++)
                    s += sZP[q * 1024 + (g * 4 + u) * 64 + gb];
                z[g] = s;
            }
            float ii = sigmoidf_(z[0]);
            float ff = sigmoidf_(z[1]);
            float gg = tanhf_(z[2]);
            float oo = sigmoidf_(z[3]);
            float cn = ff * creg + ii * gg;
            creg = cn;
            float hn = oo * tanhf_(cn);
            int j = jb * 4 + u;
            __stcg(&g_h[((dir * 2 + (par ^ 1)) * HH + j) * BB + gb], hn);
            barx(1, 256);                       // all 256 h stores issued
            if (t == 0) {
                asm volatile("membar.gl;" ::: "memory");
                st_release_gpu(slots + jb, (unsigned)(step + 1));
            }
            // off-critical-path span accumulation
            while (m) {
                int p = __ffs(m) - 1;
                m &= m - 1;
                sR[p * 256 + u * 64 + gb] += hn;
            }
        }

        // 7. trailing x-GEMM for step+1 (group X already landed)
        cpasync_wait0();
        barx(pbar, 64);
        if (step + 1 < nsteps)
            gemm_range(sAct, sW2, ct, b0, xb, xb + 16, acc);
    }

    __syncthreads();
    for (int i = t; i < 8192; i += 512) {
        int p = i >> 8, uu = (i >> 6) & 3, b = i & 63;
        g_reps[(b * PP + p) * (2 * HH) + dir * HH + jb * 4 + uu] = sR[i];
    }
}

__global__ void k_final(const float* fc_w, const float* fc_b,
                        const int* positions, float* out) {
    int bp = blockIdx.x;
    int t = threadIdx.x;
    __shared__ float red[128];
    float s = 0.f;
    for (int d = t; d < 2 * HH; d += 128)
        s += g_reps[bp * (2 * HH) + d] * fc_w[d];
    red[t] = s;
    __syncthreads();
    for (int o = 64; o > 0; o >>= 1) {
        if (t < o) red[t] += red[t + o];
        __syncthreads();
    }
    if (t == 0) {
        int cnt = g_cnt[bp];
        int ps = positions[bp * 2], pe = positions[bp * 2 + 1];
        bool valid = (cnt > 0) && !(ps == 0 && pe == 0);
        float v = valid ? red[0] / fmaxf((float)cnt, 1.f) : 0.f;
        out[bp] = v + fc_b[0];
    }
}

extern "C" void kernel_launch(void* const* d_in, const int* in_sizes, int n_in,
                              void* d_out, int out_size) {
    const float* emb    = (const float*)d_in[0];
    const float* Wih_f  = (const float*)d_in[1];
    const float* Whh_f  = (const float*)d_in[2];
    const float* bih_f  = (const float*)d_in[3];
    const float* bhh_f  = (const float*)d_in[4];
    const float* Wih_b  = (const float*)d_in[5];
    const float* Whh_b  = (const float*)d_in[6];
    const float* bih_b  = (const float*)d_in[7];
    const float* bhh_b  = (const float*)d_in[8];
    const float* fc_w   = (const float*)d_in[9];
    const float* fc_b   = (const float*)d_in[10];
    const int* input_ids = (const int*)d_in[11];
    const int* offmap    = (const int*)d_in[13];
    const int* positions = (const int*)d_in[14];
    float* out = (float*)d_out;

    cudaFuncSetAttribute(k_lstm, cudaFuncAttributeMaxDynamicSharedMemorySize, SMEM_BYTES);

    k_prep<<<1024, 256>>>(bih_f, bhh_f, bih_b, bhh_b, Wih_f, Whh_f, Wih_b, Whh_b);
    k_embed<<<SS, 256>>>(emb, input_ids);
    k_span<<<(BB * SS) / 256, 256>>>(offmap, positions);
    k_lstm<<<NBLK, 512, SMEM_BYTES>>>(SS);
    k_final<<<BB * PP, 128>>>(fc_w, fc_b, positions, out);
}

// round 17
// speedup vs baseline: 2.0696x; 1.0810x over previous
#include <cuda_runtime.h>
#include <math.h>
#include <stdint.h>

#define BB 64
#define SS 1024
#define PP 32
#define EE 128
#define HH 256
#define G4 1024
#define NJB 64
#define NBLK 128
#define SWS2 776   // 776 % 32 == 8 -> permuted-row weight loads hit banks +0/+8/+16/+24

#define SM_ACT 0
#define SM_W   24576
#define SM_Z   (SM_W + 16*SWS2)
#define SM_R   (SM_Z + 8192)
#define SM_M   (SM_R + 8192)
#define SMEM_FLOATS (SM_M + 128)
#define SMEM_BYTES (SMEM_FLOATS * 4)

__device__ float    g_xT[SS * EE * BB];
__device__ float    g_h[2 * 2 * HH * BB];
__device__ float    g_bias[2 * G4];
__device__ float    g_Wt[2 * NJB * 16 * 384 * 2];
__device__ unsigned g_spanmaskT[SS * BB];
__device__ int      g_cnt[BB * PP];
__device__ float    g_reps[BB * PP * 2 * HH];
__device__ unsigned g_arrive[2 * NJB];

__global__ void k_prep(const float* bih_f, const float* bhh_f,
                       const float* bih_b, const float* bhh_b,
                       const float* Wih_f, const float* Whh_f,
                       const float* Wih_b, const float* Whh_b) {
    int i0 = blockIdx.x * blockDim.x + threadIdx.x;
    int stride = gridDim.x * blockDim.x;
    if (i0 < 2 * NJB) g_arrive[i0] = 0;
    for (int i = i0; i < 2 * 2 * HH * BB; i += stride) g_h[i] = 0.f;
    for (int i = i0; i < BB * PP;         i += stride) g_cnt[i] = 0;
    for (int i = i0; i < 2 * G4;          i += stride)
        g_bias[i] = (i < G4) ? (bih_f[i] + bhh_f[i]) : (bih_b[i - G4] + bhh_b[i - G4]);
    for (int idx = i0; idx < 2 * NJB * 16 * 384; idx += stride) {
        int k   = idx % 384;
        int r   = idx / 384;
        int c   = r % 16;
        int jb  = (r / 16) % NJB;
        int dir = r / (16 * NJB);
        int zcol = (c >> 2) * HH + jb * 4 + (c & 3);
        const float* Wih = dir ? Wih_b : Wih_f;
        const float* Whh = dir ? Whh_b : Whh_f;
        float v = (k < EE) ? Wih[zcol * EE + k] : Whh[zcol * HH + (k - EE)];
        g_Wt[idx * 2 + 0] = v;
        g_Wt[idx * 2 + 1] = v;
    }
}

__global__ void k_embed(const float* emb, const int* ids) {
    __shared__ float tile[128 * 65];
    __shared__ int sid[64];
    int s = blockIdx.x, t = threadIdx.x;
    if (t < 64) sid[t] = ids[t * SS + s];
    __syncthreads();
    for (int i = t; i < 8192; i += 256) {
        int b = i >> 7, e = i & 127;
        tile[e * 65 + b] = emb[sid[b] * EE + e];
    }
    __syncthreads();
    float* dst = g_xT + s * (EE * BB);
    for (int i = t; i < 8192; i += 256)
        dst[i] = tile[(i >> 6) * 65 + (i & 63)];
}

__global__ void k_span(const int* offmap, const int* positions) {
    int idx = blockIdx.x * blockDim.x + threadIdx.x;
    if (idx >= BB * SS) return;
    int b = idx / SS;
    int s = idx % SS;
    int os = offmap[idx * 2], oe = offmap[idx * 2 + 1];
    unsigned m = 0;
    for (int p = 0; p < PP; p++) {
        int ps = positions[(b * PP + p) * 2];
        int pe = positions[(b * PP + p) * 2 + 1];
        if (os >= ps && oe <= pe) {
            m |= (1u << p);
            atomicAdd(&g_cnt[b * PP + p], 1);
        }
    }
    g_spanmaskT[s * BB + b] = m;
}

__device__ __forceinline__ void ffma2(unsigned long long& d,
                                      unsigned long long a,
                                      unsigned long long b) {
    asm("fma.rn.f32x2 %0, %1, %2, %0;" : "+l"(d) : "l"(a), "l"(b));
}
__device__ __forceinline__ void cpasync16(uint32_t saddr, const void* gaddr) {
    asm volatile("cp.async.cg.shared.global [%0], [%1], 16;" :: "r"(saddr), "l"(gaddr));
}
__device__ __forceinline__ void cpasync_commit() { asm volatile("cp.async.commit_group;"); }
__device__ __forceinline__ void cpasync_wait2()  { asm volatile("cp.async.wait_group 2;"); }
__device__ __forceinline__ void cpasync_wait1()  { asm volatile("cp.async.wait_group 1;"); }
__device__ __forceinline__ void cpasync_wait0()  { asm volatile("cp.async.wait_group 0;"); }
__device__ __forceinline__ void st_release_gpu(unsigned* p, unsigned v) {
    asm volatile("st.release.gpu.global.u32 [%0], %1;" :: "l"(p), "r"(v) : "memory");
}
__device__ __forceinline__ unsigned ld_acquire_gpu(const unsigned* p) {
    unsigned v;
    asm volatile("ld.acquire.gpu.global.u32 %0, [%1];" : "=r"(v) : "l"(p) : "memory");
    return v;
}
__device__ __forceinline__ void barx(int id, int cnt) {
    asm volatile("bar.sync %0, %1;" :: "r"(id), "r"(cnt) : "memory");
}
__device__ __forceinline__ float sigmoidf_(float x) {
    return __fdividef(1.f, 1.f + __expf(-x));
}
__device__ __forceinline__ float tanhf_(float x) {
    float xc = fminf(fmaxf(x, -15.f), 15.f);
    float e = __expf(2.f * xc);
    return __fdividef(e - 1.f, e + 1.f);
}

// GEMM over K range: 4 zcols (gate ct), 4 batches. Weight rows permuted in smem:
// row for (ct, r) lives at smem row (r*4 + ct)  -> simultaneous ct-loads conflict-free.
__device__ __forceinline__ void gemm_range(const float* __restrict__ sAct,
                                           const float* __restrict__ sW2,
                                           int ct, int b0, int kbeg, int kend,
                                           unsigned long long acc[4][2]) {
    const float* abase = sAct + b0;
    #pragma unroll 2
    for (int k = kbeg; k < kend; k += 4) {
        ulonglong2 a0 = *(const ulonglong2*)(abase + (k + 0) * BB);
        ulonglong2 a1 = *(const ulonglong2*)(abase + (k + 1) * BB);
        ulonglong2 a2 = *(const ulonglong2*)(abase + (k + 2) * BB);
        ulonglong2 a3 = *(const ulonglong2*)(abase + (k + 3) * BB);
        #pragma unroll
        for (int r = 0; r < 4; r++) {
            const float* wb = sW2 + (r * 4 + ct) * SWS2 + k * 2;
            ulonglong2 w01 = *(const ulonglong2*)(wb);
            ulonglong2 w23 = *(const ulonglong2*)(wb + 4);
            ffma2(acc[r][0], w01.x, a0.x); ffma2(acc[r][1], w01.x, a0.y);
            ffma2(acc[r][0], w01.y, a1.x); ffma2(acc[r][1], w01.y, a1.y);
            ffma2(acc[r][0], w23.x, a2.x); ffma2(acc[r][1], w23.x, a2.y);
            ffma2(acc[r][0], w23.y, a3.x); ffma2(acc[r][1], w23.y, a3.y);
        }
    }
}

extern __shared__ float smem[];

__global__ void __launch_bounds__(512, 1) k_lstm(int nsteps) {
    float*    sAct = smem + SM_ACT;              // [384][64]
    float*    sW2  = smem + SM_W;                // [16][SWS2], rows permuted r*4+ct
    float*    sZP  = smem + SM_Z;                // [8 kq][16][64]
    float*    sR   = smem + SM_R;                // [32 p][4 u][64 b]
    unsigned* sM   = (unsigned*)(smem + SM_M);   // [2][64]

    const int t   = threadIdx.x;
    const int jb  = blockIdx.x & (NJB - 1);
    const int dir = blockIdx.x >> 6;
    unsigned* slots = g_arrive + dir * NJB;

    {   // weights resident in smem, rows permuted: src row c -> dst row (c&3)*4 + (c>>2)
        const float4* wsrc = (const float4*)(g_Wt + (size_t)(dir * NJB + jb) * 16 * 384 * 2);
        float4* wdst = (float4*)sW2;
        for (int i = t; i < 3072; i += 512) {
            int c = i / 192, j = i % 192;
            int cp = (c & 3) * 4 + (c >> 2);
            wdst[cp * (SWS2 / 4) + j] = wsrc[i];
        }
    }
    for (int i = t; i < 8192; i += 512) sR[i] = 0.f;

    // GEMM roles: warp batch-split within pair (act loads deduplicated)
    const int kq    = t >> 6;           // warp-pair id 0..7
    const int tp    = t & 63;
    const int wl    = tp >> 5;          // warp within pair 0/1
    const int lane  = tp & 31;
    const int ct    = lane >> 3;        // gate 0..3 (all four in each warp)
    const int b0    = ((lane & 7) + wl * 8) * 4;   // warp0: batches 0..31, warp1: 32..63
    const int hb    = 128 + kq * 32;
    const int xb    = kq * 16;
    const int pbar  = 8 + kq;

    // gates roles (t<256): 1 cell per thread
    const int u  = (t >> 6) & 3;
    const int gb = t & 63;
    float bvg[4];
    if (t < 256) {
        #pragma unroll
        for (int g = 0; g < 4; g++)
            bvg[g] = g_bias[dir * G4 + g * HH + jb * 4 + u];
    }
    float creg = 0.f;

    const uint32_t sact_b = (uint32_t)__cvta_generic_to_shared(sAct);
    const uint32_t sm_b   = (uint32_t)__cvta_generic_to_shared(sM);

    unsigned long long acc[4][2];

    // prologue: pair-local x(step0) + mask(step0), x-GEMM(0)
    {
        int s0 = dir ? (SS - 1) : 0;
        const float* xsrc = g_xT + (size_t)s0 * (EE * BB);
        #pragma unroll
        for (int i = 0; i < 4; i++) {
            int fi = kq * 1024 + (i * 64 + tp) * 4;
            cpasync16(sact_b + (uint32_t)fi * 4, xsrc + fi);
        }
        if (t < 16)
            cpasync16(sm_b + (uint32_t)t * 16, g_spanmaskT + s0 * BB + t * 4);
        cpasync_commit();
    }
    cpasync_wait0();
    __syncthreads();
    #pragma unroll
    for (int r = 0; r < 4; r++) { acc[r][0] = 0ull; acc[r][1] = 0ull; }
    gemm_range(sAct, sW2, ct, b0, xb, xb + 16, acc);
    barx(pbar, 64);
    if (nsteps > 1) {
        int s1 = dir ? (SS - 2) : 1;
        const float* xsrc = g_xT + (size_t)s1 * (EE * BB);
        #pragma unroll
        for (int i = 0; i < 4; i++) {
            int fi = kq * 1024 + (i * 64 + tp) * 4;
            cpasync16(sact_b + (uint32_t)fi * 4, xsrc + fi);
        }
    }
    cpasync_commit();

    for (int step = 0; step < nsteps; step++) {
        const int par = step & 1;

        // 1. slot barrier (only 64 threads poll)
        if (t < NJB) {
            while ((int)ld_acquire_gpu(slots + t) < step) { }
        }
        __syncthreads();

        // 2. pair-local h staging in TWO waves (groups A, B)
        {
            const float* hsrc = g_h + (dir * 2 + par) * (HH * BB);
            #pragma unroll
            for (int i = 0; i < 4; i++) {
                int fi = kq * 2048 + (i * 64 + tp) * 4;
                cpasync16(sact_b + (uint32_t)(8192 + fi) * 4, hsrc + fi);
            }
            cpasync_commit();
            #pragma unroll
            for (int i = 4; i < 8; i++) {
                int fi = kq * 2048 + (i * 64 + tp) * 4;
                cpasync16(sact_b + (uint32_t)(8192 + fi) * 4, hsrc + fi);
            }
            cpasync_commit();
        }

        // 3. x + mask prefetch for step+1 (group X)
        if (step + 1 < nsteps) {
            int s_next = dir ? (SS - 2 - step) : (step + 1);
            const float* xsrc = g_xT + (size_t)s_next * (EE * BB);
            #pragma unroll
            for (int i = 0; i < 4; i++) {
                int fi = kq * 1024 + (i * 64 + tp) * 4;
                cpasync16(sact_b + (uint32_t)fi * 4, xsrc + fi);
            }
            if (t < 16)
                cpasync16(sm_b + (uint32_t)((par ^ 1) * 64 + t * 4) * 4,
                          g_spanmaskT + s_next * BB + t * 4);
        }
        cpasync_commit();

        // 4. h-GEMM: wave A while wave B lands, then wave B
        cpasync_wait2();
        barx(pbar, 64);
        gemm_range(sAct, sW2, ct, b0, hb, hb + 16, acc);
        cpasync_wait1();
        barx(pbar, 64);
        gemm_range(sAct, sW2, ct, b0, hb + 16, hb + 32, acc);

        // 5. K-eighth partials; block-wide join
        #pragma unroll
        for (int r = 0; r < 4; r++) {
            float2 lo = *(float2*)&acc[r][0];
            float2 hi = *(float2*)&acc[r][1];
            *(float4*)&sZP[kq * 1024 + (ct * 4 + r) * 64 + b0] =
                make_float4(lo.x, lo.y, hi.x, hi.y);
        }
        #pragma unroll
        for (int r = 0; r < 4; r++) { acc[r][0] = 0ull; acc[r][1] = 0ull; }
        __syncthreads();

        // 6. gates (warps 0-7); warps 8-15 fall through to trailing x-GEMM
        if (t < 256) {
            unsigned m = sM[par * 64 + gb];
            float z[4];
            #pragma unroll
            for (int g = 0; g < 4; g++) {
                float s = bvg[g];
                #pragma unroll
                for (int q = 0; q < 8; q++)
                    s += sZP[q * 1024 + (g * 4 + u) * 64 + gb];
                z[g] = s;
            }
            float ii = sigmoidf_(z[0]);
            float ff = sigmoidf_(z[1]);
            float gg = tanhf_(z[2]);
            float oo = sigmoidf_(z[3]);
            float cn = ff * creg + ii * gg;
            creg = cn;
            float hn = oo * tanhf_(cn);
            int j = jb * 4 + u;
            __stcg(&g_h[((dir * 2 + (par ^ 1)) * HH + j) * BB + gb], hn);
            barx(1, 256);
            if (t == 0) {
                asm volatile("membar.gl;" ::: "memory");
                st_release_gpu(slots + jb, (unsigned)(step + 1));
            }
            while (m) {
                int p = __ffs(m) - 1;
                m &= m - 1;
                sR[p * 256 + u * 64 + gb] += hn;
            }
        }

        // 7. trailing x-GEMM for step+1
        cpasync_wait0();
        barx(pbar, 64);
        if (step + 1 < nsteps)
            gemm_range(sAct, sW2, ct, b0, xb, xb + 16, acc);
    }

    __syncthreads();
    for (int i = t; i < 8192; i += 512) {
        int p = i >> 8, uu = (i >> 6) & 3, b = i & 63;
        g_reps[(b * PP + p) * (2 * HH) + dir * HH + jb * 4 + uu] = sR[i];
    }
}

__global__ void k_final(const float* fc_w, const float* fc_b,
                        const int* positions, float* out) {
    int bp = blockIdx.x;
    int t = threadIdx.x;
    __shared__ float red[128];
    float s = 0.f;
    for (int d = t; d < 2 * HH; d += 128)
        s += g_reps[bp * (2 * HH) + d] * fc_w[d];
    red[t] = s;
    __syncthreads();
    for (int o = 64; o > 0; o >>= 1) {
        if (t < o) red[t] += red[t + o];
        __syncthreads();
    }
    if (t == 0) {
        int cnt = g_cnt[bp];
        int ps = positions[bp * 2], pe = positions[bp * 2 + 1];
        bool valid = (cnt > 0) && !(ps == 0 && pe == 0);
        float v = valid ? red[0] / fmaxf((float)cnt, 1.f) : 0.f;
        out[bp] = v + fc_b[0];
    }
}

extern "C" void kernel_launch(void* const* d_in, const int* in_sizes, int n_in,
                              void* d_out, int out_size) {
    const float* emb    = (const float*)d_in[0];
    const float* Wih_f  = (const float*)d_in[1];
    const float* Whh_f  = (const float*)d_in[2];
    const float* bih_f  = (const float*)d_in[3];
    const float* bhh_f  = (const float*)d_in[4];
    const float* Wih_b  = (const float*)d_in[5];
    const float* Whh_b  = (const float*)d_in[6];
    const float* bih_b  = (const float*)d_in[7];
    const float* bhh_b  = (const float*)d_in[8];
    const float* fc_w   = (const float*)d_in[9];
    const float* fc_b   = (const float*)d_in[10];
    const int* input_ids = (const int*)d_in[11];
    const int* offmap    = (const int*)d_in[13];
    const int* positions = (const int*)d_in[14];
    float* out = (float*)d_out;

    cudaFuncSetAttribute(k_lstm, cudaFuncAttributeMaxDynamicSharedMemorySize, SMEM_BYTES);

    k_prep<<<1024, 256>>>(bih_f, bhh_f, bih_b, bhh_b, Wih_f, Whh_f, Wih_b, Whh_b);
    k_embed<<<SS, 256>>>(emb, input_ids);
    k_span<<<(BB * SS) / 256, 256>>>(offmap, positions);
    k_lstm<<<NBLK, 512, SMEM_BYTES>>>(SS);
    k_final<<<BB * PP, 128>>>(fc_w, fc_b, positions, out);
}